// round 12
// baseline (speedup 1.0000x reference)
#include <cuda_runtime.h>
#include <cuda_bf16.h>
#include <cstdint>
#include <math.h>

#define SPATIAL 196608           // 24*64*128
#define NELEM_B (32 * SPATIAL)   // per-batch elements of cost

// per-launch-overwritten scratch (no zeroing needed; deterministic across graph replays)
static __device__ float g_p1s[1024], g_p1q[1024];      // GN1 per-block partials
static __device__ float g_p2s[296],  g_p2q[296];       // GN2 per-block partials
static __device__ __nv_bfloat16 g_Kbf[2][2][256][16];  // pre-scaled by 0.25*log2(e)
static __device__ __nv_bfloat16 g_Vbf[2][2][256][16];

// ---- prologue: blocks 0..1023 = GN1 stats partials; blocks 1024..1087 = K/V projection ----
__global__ void prologue_kernel(const float* __restrict__ cost,
                                const float* __restrict__ feat,
                                const float* __restrict__ Wk,
                                const float* __restrict__ Wv) {
    __shared__ float rs[256], rss[256];
    const int blk = blockIdx.x;
    const int tid = threadIdx.x;

    if (blk >= 1024) {   // K/V projection: 64 blocks * 256 threads = 16384 outputs
        int idx = (blk - 1024) * 256 + tid;
        int c = idx & 15, n = (idx >> 4) & 255, h = (idx >> 12) & 1, b = idx >> 13;
        const float* f  = feat + (size_t)b * 65536 + n;   // stride 256 per fc
        const float* wk = Wk + (h * 16 + c) * 256;
        const float* wv = Wv + (h * 16 + c) * 256;
        float sk = 0.f, sv = 0.f;
        #pragma unroll 8
        for (int fc = 0; fc < 256; ++fc) {
            float fv = f[(size_t)fc * 256];
            sk = fmaf(wk[fc], fv, sk);
            sv = fmaf(wv[fc], fv, sv);
        }
        g_Kbf[b][h][n][c] = __float2bfloat16(sk * 0.36067376022224085f); // 0.25*log2e
        g_Vbf[b][h][n][c] = __float2bfloat16(sv);
        return;
    }

    const int b = blk >> 9;
    const float4* p = (const float4*)(cost + (size_t)b * NELEM_B);
    const int n4 = NELEM_B / 4;
    float s = 0.f, ss = 0.f;
    for (int i = (blk & 511) * 256 + tid; i < n4; i += 512 * 256) {
        float4 v = p[i];
        s  += (v.x + v.y) + (v.z + v.w);
        ss += (v.x * v.x + v.y * v.y) + (v.z * v.z + v.w * v.w);
    }
    rs[tid] = s; rss[tid] = ss;
    __syncthreads();
    for (int st = 128; st > 0; st >>= 1) {
        if (tid < st) { rs[tid] += rs[tid + st]; rss[tid] += rss[tid + st]; }
        __syncthreads();
    }
    if (tid == 0) { g_p1s[blk] = rs[0]; g_p1q[blk] = rss[0]; }
}

__device__ __forceinline__ void mma_bf16(float* c, const uint32_t* a, const uint32_t* b) {
    asm volatile(
        "mma.sync.aligned.m16n8k16.row.col.f32.bf16.bf16.f32 "
        "{%0,%1,%2,%3}, {%4,%5,%6,%7}, {%8,%9}, {%0,%1,%2,%3};\n"
        : "+f"(c[0]), "+f"(c[1]), "+f"(c[2]), "+f"(c[3])
        : "r"(a[0]), "r"(a[1]), "r"(a[2]), "r"(a[3]), "r"(b[0]), "r"(b[1]));
}

__device__ __forceinline__ void ldmatrix_x4(uint32_t& r0, uint32_t& r1, uint32_t& r2, uint32_t& r3, uint32_t addr) {
    asm volatile("ldmatrix.sync.aligned.m8n8.x4.shared.b16 {%0,%1,%2,%3}, [%4];"
        : "=r"(r0), "=r"(r1), "=r"(r2), "=r"(r3) : "r"(addr));
}

__device__ __forceinline__ uint32_t pack_bf16x2(float lo, float hi) {
    __nv_bfloat162 p = __float22bfloat162_rn(make_float2(lo, hi));
    return *(uint32_t*)&p;
}

__device__ __forceinline__ float ex2f(float x) {
    float y; asm("ex2.approx.f32 %0, %1;" : "=f"(y) : "f"(x)); return y;
}

// QK logits for one 16-token chunk (4 mmas). KhL pre-offset by g*24+tg*2.
__device__ __forceinline__ void qk_chunk(const __nv_bfloat16* KhL, int n0,
                                         const uint32_t (&aqh)[2][4], float (&cl)[2][2][4]) {
    uint32_t bk[2][2];
    #pragma unroll
    for (int nt = 0; nt < 2; ++nt) {
        const __nv_bfloat16* kp = KhL + (n0 + nt * 8) * 24;
        bk[nt][0] = *(const uint32_t*)kp;
        bk[nt][1] = *(const uint32_t*)(kp + 8);
    }
    #pragma unroll
    for (int mt = 0; mt < 2; ++mt)
        #pragma unroll
        for (int nt = 0; nt < 2; ++nt) {
            cl[mt][nt][0] = cl[mt][nt][1] = cl[mt][nt][2] = cl[mt][nt][3] = 0.f;
            mma_bf16(cl[mt][nt], aqh[mt], bk[nt]);
        }
}

// exp2 + pack + PV accumulate for one chunk (6 mmas). VhL pre-offset by g*264+tg*2.
__device__ __forceinline__ void pv_chunk(const __nv_bfloat16* VhL, int n0,
                                         float (&cl)[2][2][4], float (&co)[2][3][4]) {
    #pragma unroll
    for (int mt = 0; mt < 2; ++mt)
        #pragma unroll
        for (int nt = 0; nt < 2; ++nt)
            #pragma unroll
            for (int i = 0; i < 4; ++i)
                cl[mt][nt][i] = ex2f(cl[mt][nt][i]);
    uint32_t ap[2][4];
    #pragma unroll
    for (int mt = 0; mt < 2; ++mt) {
        ap[mt][0] = pack_bf16x2(cl[mt][0][0], cl[mt][0][1]);
        ap[mt][1] = pack_bf16x2(cl[mt][0][2], cl[mt][0][3]);
        ap[mt][2] = pack_bf16x2(cl[mt][1][0], cl[mt][1][1]);
        ap[mt][3] = pack_bf16x2(cl[mt][1][2], cl[mt][1][3]);
    }
    uint32_t bv[3][2];
    #pragma unroll
    for (int nv = 0; nv < 3; ++nv) {
        const __nv_bfloat16* vp = VhL + nv * 2112 + n0;   // 2112 = 8*264
        bv[nv][0] = *(const uint32_t*)vp;
        bv[nv][1] = *(const uint32_t*)(vp + 8);
    }
    #pragma unroll
    for (int mt = 0; mt < 2; ++mt)
        #pragma unroll
        for (int nv = 0; nv < 3; ++nv)
            mma_bf16(co[mt][nv], ap[mt], bv[nv]);
}

// smem layout (bytes):
//   Ks   [2][256][24] bf16 : 0     .. 24576   (cols 0..15 valid)
//   Vt   [2][24][264] bf16 : 24576 .. 49920   (row16 = ones, 17..23 = zeros)
//   sGw/sGb 32 f32 each    : 49920 .. 50176
//   sWqf [16][32] u32      : 50176 .. 52224   (pre-packed Wq B-frags per lane, 2048 B)
//   sWof [16][32] u32      : 52224 .. 54272   (2048 B)
//   X scratch 8 w * 2560B  : 54272 .. 74752
#define SMEM_TOTAL 74752

__global__ void __launch_bounds__(256, 2) main_kernel(
    const float* __restrict__ cost,
    const float* __restrict__ Wq,
    const float* __restrict__ Wo,
    const float* __restrict__ gnw,
    const float* __restrict__ gnb,
    const float* __restrict__ gammap,
    float* __restrict__ out)
{
    extern __shared__ char sm[];
    __nv_bfloat16* Ks = (__nv_bfloat16*)sm;
    __nv_bfloat16* Vt = (__nv_bfloat16*)(sm + 24576);
    float*    sGw  = (float*)(sm + 49920);
    float*    sGb  = (float*)(sm + 50048);
    uint32_t* sWqf = (uint32_t*)(sm + 50176);
    uint32_t* sWof = (uint32_t*)(sm + 52224);
    char*  scratch = sm + 54272;
    __shared__ float rs[256], rss[256];
    __shared__ float sMuIs[2];

    const int b   = blockIdx.x & 1;
    const int bi  = blockIdx.x >> 1;
    const int tid = threadIdx.x;
    const int wid = tid >> 5;
    const int lane = tid & 31;
    const int g  = lane >> 2;
    const int tg = lane & 3;

    // ---- GN1 stats from prologue partials (pairwise fp32 tree, double finish) ----
    {
        float ps = 0.f, pq = 0.f;
        #pragma unroll
        for (int i = tid; i < 512; i += 256) { ps += g_p1s[b * 512 + i]; pq += g_p1q[b * 512 + i]; }
        rs[tid] = ps; rss[tid] = pq;
        __syncthreads();
        for (int st = 128; st > 0; st >>= 1) {
            if (tid < st) { rs[tid] += rs[tid + st]; rss[tid] += rss[tid + st]; }
            __syncthreads();
        }
        if (tid == 0) {
            double mu  = (double)rs[0] / (double)NELEM_B;
            double var = (double)rss[0] / (double)NELEM_B - mu * mu;
            sMuIs[0] = (float)mu;
            sMuIs[1] = (float)(1.0 / sqrt(var + 1e-5));
        }
        __syncthreads();
    }
    if (tid < 32) {
        float sc = gnw[tid] * sMuIs[1];
        sGw[tid] = sc;
        sGb[tid] = gnb[tid] - sMuIs[0] * sc;
    }

    // ---- K (token-major) and V (transposed + ones column) to smem ----
    for (int i = tid; i < 512; i += 256) {          // i = h*256 + n
        int h = i >> 8, n = i & 255;
        const uint4* kp = (const uint4*)&g_Kbf[b][h][n][0];
        __nv_bfloat16* krow = Ks + i * 24;
        ((uint4*)krow)[0] = kp[0];
        *(uint4*)(krow + 8) = kp[1];
        const __nv_bfloat16* vp = &g_Vbf[b][h][n][0];
        #pragma unroll
        for (int c = 0; c < 16; ++c) Vt[(h * 24 + c) * 264 + n] = vp[c];
        Vt[(h * 24 + 16) * 264 + n] = __float2bfloat16(1.0f);
        #pragma unroll
        for (int c = 17; c < 24; ++c) Vt[(h * 24 + c) * 264 + n] = __float2bfloat16(0.0f);
    }

    // ---- pre-packed per-lane B-fragments of Wq / Wo into smem ----
    if (tid < 32) {
        #pragma unroll
        for (int nt = 0; nt < 4; ++nt)
            #pragma unroll
            for (int kc = 0; kc < 2; ++kc) {
                const float* wq = Wq + (nt * 8 + g) * 32 + kc * 16 + tg * 2;
                const float* wo = Wo + (nt * 8 + g) * 32 + kc * 16 + tg * 2;
                int j = nt * 4 + kc * 2;
                sWqf[(j + 0) * 32 + lane] = pack_bf16x2(wq[0], wq[1]);
                sWqf[(j + 1) * 32 + lane] = pack_bf16x2(wq[8], wq[9]);
                sWof[(j + 0) * 32 + lane] = pack_bf16x2(wo[0], wo[1]);
                sWof[(j + 1) * 32 + lane] = pack_bf16x2(wo[8], wo[9]);
            }
    }
    __syncthreads();

    const float gamma = *gammap;
    const float* costb = cost + (size_t)b * NELEM_B;
    float* outb = out + (size_t)b * NELEM_B;

    __nv_bfloat16* X = (__nv_bfloat16*)(scratch + wid * 2560);  // [32][40] bf16
    const uint32_t xu = (uint32_t)__cvta_generic_to_shared(X);

    float lsum = 0.f, lsumsq = 0.f;

    for (int super = bi; super < 768; super += 148) {
        const int vbase = super * 256 + wid * 32;
        const int v = vbase + lane;

        // ---- GN1-normalize -> bf16 X in smem ----
        {
            uint32_t xp[16];
            #pragma unroll
            for (int j = 0; j < 16; ++j) {
                float a0 = fmaf(costb[(size_t)(2 * j) * SPATIAL + v],     sGw[2 * j],     sGb[2 * j]);
                float a1 = fmaf(costb[(size_t)(2 * j + 1) * SPATIAL + v], sGw[2 * j + 1], sGb[2 * j + 1]);
                xp[j] = pack_bf16x2(a0, a1);
            }
            uint4* xr = (uint4*)((char*)X + lane * 80);
            xr[0] = make_uint4(xp[0], xp[1], xp[2], xp[3]);
            xr[1] = make_uint4(xp[4], xp[5], xp[6], xp[7]);
            xr[2] = make_uint4(xp[8], xp[9], xp[10], xp[11]);
            xr[3] = make_uint4(xp[12], xp[13], xp[14], xp[15]);
        }
        __syncwarp();

        // ---- A-fragments of X via ldmatrix ----
        uint32_t aX[2][2][4];
        {
            const uint32_t lrow = (uint32_t)(lane & 15) * 80 + (uint32_t)(lane >> 4) * 16;
            #pragma unroll
            for (int mt = 0; mt < 2; ++mt)
                #pragma unroll
                for (int kc = 0; kc < 2; ++kc)
                    ldmatrix_x4(aX[mt][kc][0], aX[mt][kc][1], aX[mt][kc][2], aX[mt][kc][3],
                                xu + (uint32_t)mt * 1280 + (uint32_t)kc * 32 + lrow);
        }
        __syncwarp();  // X reads done before next iteration's writes

        // ---- q = X @ Wq^T (frags from smem; registers transient) ----
        float qc[2][4][4];
        {
            uint32_t bwqf[16];
            #pragma unroll
            for (int j = 0; j < 16; ++j) bwqf[j] = sWqf[j * 32 + lane];
            #pragma unroll
            for (int mt = 0; mt < 2; ++mt)
                #pragma unroll
                for (int nt = 0; nt < 4; ++nt) {
                    #pragma unroll
                    for (int i = 0; i < 4; ++i) qc[mt][nt][i] = 0.f;
                    mma_bf16(qc[mt][nt], aX[mt][0], &bwqf[nt * 4 + 0]);
                    mma_bf16(qc[mt][nt], aX[mt][1], &bwqf[nt * 4 + 2]);
                }
        }

        // C-frag -> A-frag identity: per-head QK A operands
        uint32_t aq[2][2][4];
        #pragma unroll
        for (int h = 0; h < 2; ++h)
            #pragma unroll
            for (int mt = 0; mt < 2; ++mt) {
                aq[h][mt][0] = pack_bf16x2(qc[mt][2 * h][0],     qc[mt][2 * h][1]);
                aq[h][mt][1] = pack_bf16x2(qc[mt][2 * h][2],     qc[mt][2 * h][3]);
                aq[h][mt][2] = pack_bf16x2(qc[mt][2 * h + 1][0], qc[mt][2 * h + 1][1]);
                aq[h][mt][3] = pack_bf16x2(qc[mt][2 * h + 1][2], qc[mt][2 * h + 1][3]);
            }

        // ---- attention per head, software-pipelined chunks ----
        uint32_t aA[2][2][4];   // [mt][kc=h][4]
        #pragma unroll
        for (int h = 0; h < 2; ++h) {
            const __nv_bfloat16* KhL = Ks + h * 6144 + g * 24  + tg * 2;
            const __nv_bfloat16* VhL = Vt + h * 6336 + g * 264 + tg * 2;
            float co[2][3][4];
            #pragma unroll
            for (int mt = 0; mt < 2; ++mt)
                #pragma unroll
                for (int nv = 0; nv < 3; ++nv)
                    #pragma unroll
                    for (int i = 0; i < 4; ++i) co[mt][nv][i] = 0.f;

            float clA[2][2][4], clB[2][2][4];
            qk_chunk(KhL, 0, aq[h], clA);
            #pragma unroll
            for (int cc = 0; cc < 8; ++cc) {
                qk_chunk(KhL, (2 * cc + 1) * 16, aq[h], clB);   // prefetch next QK
                pv_chunk(VhL, (2 * cc) * 16, clA, co);
                if (cc < 7) qk_chunk(KhL, (2 * cc + 2) * 16, aq[h], clA);
                pv_chunk(VhL, (2 * cc + 1) * 16, clB, co);
            }

            // normalize (ones-column denominator: dv16 -> tile 2, col 0) and pack
            #pragma unroll
            for (int mt = 0; mt < 2; ++mt) {
                float dlo = __shfl_sync(0xffffffffu, co[mt][2][0], lane & ~3);
                float dhi = __shfl_sync(0xffffffffu, co[mt][2][2], lane & ~3);
                float ilo = 1.f / dlo, ihi = 1.f / dhi;
                aA[mt][h][0] = pack_bf16x2(co[mt][0][0] * ilo, co[mt][0][1] * ilo);
                aA[mt][h][1] = pack_bf16x2(co[mt][0][2] * ihi, co[mt][0][3] * ihi);
                aA[mt][h][2] = pack_bf16x2(co[mt][1][0] * ilo, co[mt][1][1] * ilo);
                aA[mt][h][3] = pack_bf16x2(co[mt][1][2] * ihi, co[mt][1][3] * ihi);
            }
        }

        // ---- y = ao @ Wo^T (frags from smem) ----
        float yc[2][4][4];
        {
            uint32_t bwof[16];
            #pragma unroll
            for (int j = 0; j < 16; ++j) bwof[j] = sWof[j * 32 + lane];
            #pragma unroll
            for (int mt = 0; mt < 2; ++mt)
                #pragma unroll
                for (int nt = 0; nt < 4; ++nt) {
                    #pragma unroll
                    for (int i = 0; i < 4; ++i) yc[mt][nt][i] = 0.f;
                    mma_bf16(yc[mt][nt], aA[mt][0], &bwof[nt * 4 + 0]);
                    mma_bf16(yc[mt][nt], aA[mt][1], &bwof[nt * 4 + 2]);
                }
        }

        // ---- epilogue on fragments: residual + store + GN2 stats (incremental addressing) ----
        #pragma unroll
        for (int mt = 0; mt < 2; ++mt) {
            const size_t base = (size_t)(tg * 2) * SPATIAL + (size_t)(vbase + mt * 16 + g);
            const float* cp = costb + base;
            float*       op = outb  + base;
            #pragma unroll
            for (int nt = 0; nt < 4; ++nt) {
                float y0 = fmaf(gamma, yc[mt][nt][0], cp[0]);
                float y1 = fmaf(gamma, yc[mt][nt][1], cp[SPATIAL]);
                float y2 = fmaf(gamma, yc[mt][nt][2], cp[8]);
                float y3 = fmaf(gamma, yc[mt][nt][3], cp[SPATIAL + 8]);
                op[0] = y0; op[SPATIAL] = y1; op[8] = y2; op[SPATIAL + 8] = y3;
                lsum += (y0 + y1) + (y2 + y3);
                lsumsq = fmaf(y0, y0, lsumsq);
                lsumsq = fmaf(y1, y1, lsumsq);
                lsumsq = fmaf(y2, y2, lsumsq);
                lsumsq = fmaf(y3, y3, lsumsq);
                cp += (size_t)8 * SPATIAL;
                op += (size_t)8 * SPATIAL;
            }
        }
    }

    __syncthreads();
    rs[tid] = lsum; rss[tid] = lsumsq;
    __syncthreads();
    for (int st = 128; st > 0; st >>= 1) {
        if (tid < st) { rs[tid] += rs[tid + st]; rss[tid] += rss[tid + st]; }
        __syncthreads();
    }
    if (tid == 0) { g_p2s[blockIdx.x] = rs[0]; g_p2q[blockIdx.x] = rss[0]; }
}

// Final GroupNorm over y (in place on d_out); reduces the 296 GN2 partials per block
__global__ void gn2_kernel(float* __restrict__ y,
                           const float* __restrict__ w,
                           const float* __restrict__ bb) {
    __shared__ float4 red[256];
    __shared__ float prm[4];
    const int tid = threadIdx.x;
    {
        float s0 = 0.f, q0 = 0.f, s1 = 0.f, q1 = 0.f;
        for (int i = tid; i < 296; i += 256) {
            float s = g_p2s[i], q = g_p2q[i];
            if (i & 1) { s1 += s; q1 += q; } else { s0 += s; q0 += q; }
        }
        red[tid] = make_float4(s0, q0, s1, q1);
        __syncthreads();
        for (int st = 128; st > 0; st >>= 1) {
            if (tid < st) {
                float4 a = red[tid], c = red[tid + st];
                red[tid] = make_float4(a.x + c.x, a.y + c.y, a.z + c.z, a.w + c.w);
            }
            __syncthreads();
        }
        if (tid == 0) {
            double N = (double)NELEM_B;
            double mu0 = red[0].x / N, v0 = red[0].y / N - mu0 * mu0;
            double mu1 = red[0].z / N, v1 = red[0].w / N - mu1 * mu1;
            prm[0] = (float)mu0; prm[1] = (float)(1.0 / sqrt(v0 + 1e-5));
            prm[2] = (float)mu1; prm[3] = (float)(1.0 / sqrt(v1 + 1e-5));
        }
        __syncthreads();
    }
    const float m0 = prm[0], is0 = prm[1], m1 = prm[2], is1 = prm[3];

    const int half4  = NELEM_B / 4;
    const int total4 = 2 * half4;
    float4* p = (float4*)y;
    for (int i = blockIdx.x * blockDim.x + tid; i < total4; i += gridDim.x * blockDim.x) {
        int b = (i >= half4);
        int e = (i - b * half4) * 4;
        int c = e / SPATIAL;
        float is = b ? is1 : is0;
        float mu = b ? m1  : m0;
        float sc = w[c] * is;
        float sh = bb[c] - mu * sc;
        float4 val = p[i];
        val.x = fmaf(val.x, sc, sh);
        val.y = fmaf(val.y, sc, sh);
        val.z = fmaf(val.z, sc, sh);
        val.w = fmaf(val.w, sc, sh);
        p[i] = val;
    }
}

extern "C" void kernel_launch(void* const* d_in, const int* in_sizes, int n_in,
                              void* d_out, int out_size) {
    const float* cost   = (const float*)d_in[0];
    const float* feat   = (const float*)d_in[1];
    const float* Wq     = (const float*)d_in[2];
    const float* Wk     = (const float*)d_in[3];
    const float* Wv     = (const float*)d_in[4];
    const float* Wo     = (const float*)d_in[5];
    const float* gn_in_w  = (const float*)d_in[6];
    const float* gn_in_b  = (const float*)d_in[7];
    const float* gn_out_w = (const float*)d_in[8];
    const float* gn_out_b = (const float*)d_in[9];
    const float* gamma    = (const float*)d_in[10];
    float* out = (float*)d_out;

    cudaFuncSetAttribute(main_kernel, cudaFuncAttributeMaxDynamicSharedMemorySize, SMEM_TOTAL);

    prologue_kernel<<<1088, 256>>>(cost, feat, Wk, Wv);
    main_kernel<<<296, 256, SMEM_TOTAL>>>(cost, Wq, Wo, gn_in_w, gn_in_b, gamma, out);
    gn2_kernel<<<2368, 256>>>(out, gn_out_w, gn_out_b);
}

// round 15
// speedup vs baseline: 1.1784x; 1.1784x over previous
#include <cuda_runtime.h>
#include <cuda_bf16.h>
#include <cstdint>
#include <math.h>

#define SPATIAL 196608           // 24*64*128
#define NELEM_B (32 * SPATIAL)   // per-batch elements of cost

// per-launch-overwritten scratch (no zeroing needed; deterministic across graph replays)
static __device__ float g_p1s[1024], g_p1q[1024];      // GN1 per-block partials
static __device__ float g_p2s[296],  g_p2q[296];       // GN2 per-block partials
static __device__ __nv_bfloat16 g_Kbf[2][2][256][16];  // pre-scaled by 0.25*log2(e)
static __device__ __nv_bfloat16 g_Vbf[2][2][256][16];

// ---- prologue: blocks 0..63 = K/V projection (first: overlaps stats wave);
//                blocks 64..1087 = GN1 stats partials ----
__global__ void prologue_kernel(const float* __restrict__ cost,
                                const float* __restrict__ feat,
                                const float* __restrict__ Wk,
                                const float* __restrict__ Wv) {
    __shared__ float rs[256], rss[256];
    const int blk = blockIdx.x;
    const int tid = threadIdx.x;

    if (blk < 64) {   // K/V projection: 64 blocks * 256 threads = 16384 outputs
        int idx = blk * 256 + tid;
        int c = idx & 15, n = (idx >> 4) & 255, h = (idx >> 12) & 1, b = idx >> 13;
        const float* f  = feat + (size_t)b * 65536 + n;   // stride 256 per fc
        const float* wk = Wk + (h * 16 + c) * 256;
        const float* wv = Wv + (h * 16 + c) * 256;
        float sk = 0.f, sv = 0.f;
        #pragma unroll 8
        for (int fc = 0; fc < 256; ++fc) {
            float fv = f[(size_t)fc * 256];
            sk = fmaf(wk[fc], fv, sk);
            sv = fmaf(wv[fc], fv, sv);
        }
        g_Kbf[b][h][n][c] = __float2bfloat16(sk * 0.36067376022224085f); // 0.25*log2e
        g_Vbf[b][h][n][c] = __float2bfloat16(sv);
        return;
    }

    // GN1 stats: exactly 12 fixed iterations per thread (NELEM_B/4 = 12*131072)
    const int sblk = blk - 64;            // 0..1023
    const int b = sblk >> 9;
    const float4* p = (const float4*)(cost + (size_t)b * NELEM_B) + (sblk & 511) * 256 + tid;
    float4 sa = make_float4(0.f, 0.f, 0.f, 0.f);
    float4 sb = make_float4(0.f, 0.f, 0.f, 0.f);
    float4 qa = make_float4(0.f, 0.f, 0.f, 0.f);
    float4 qb = make_float4(0.f, 0.f, 0.f, 0.f);
    #pragma unroll 4
    for (int it = 0; it < 12; ++it) {
        float4 v = p[(size_t)it * 131072];
        if (it & 1) {
            sb.x += v.x; sb.y += v.y; sb.z += v.z; sb.w += v.w;
            qb.x = fmaf(v.x, v.x, qb.x); qb.y = fmaf(v.y, v.y, qb.y);
            qb.z = fmaf(v.z, v.z, qb.z); qb.w = fmaf(v.w, v.w, qb.w);
        } else {
            sa.x += v.x; sa.y += v.y; sa.z += v.z; sa.w += v.w;
            qa.x = fmaf(v.x, v.x, qa.x); qa.y = fmaf(v.y, v.y, qa.y);
            qa.z = fmaf(v.z, v.z, qa.z); qa.w = fmaf(v.w, v.w, qa.w);
        }
    }
    float s  = ((sa.x + sa.y) + (sa.z + sa.w)) + ((sb.x + sb.y) + (sb.z + sb.w));
    float ss = ((qa.x + qa.y) + (qa.z + qa.w)) + ((qb.x + qb.y) + (qb.z + qb.w));

    rs[tid] = s; rss[tid] = ss;
    __syncthreads();
    for (int st = 128; st > 0; st >>= 1) {
        if (tid < st) { rs[tid] += rs[tid + st]; rss[tid] += rss[tid + st]; }
        __syncthreads();
    }
    if (tid == 0) { g_p1s[sblk] = rs[0]; g_p1q[sblk] = rss[0]; }
}

__device__ __forceinline__ void mma_bf16(float* c, const uint32_t* a, const uint32_t* b) {
    asm volatile(
        "mma.sync.aligned.m16n8k16.row.col.f32.bf16.bf16.f32 "
        "{%0,%1,%2,%3}, {%4,%5,%6,%7}, {%8,%9}, {%0,%1,%2,%3};\n"
        : "+f"(c[0]), "+f"(c[1]), "+f"(c[2]), "+f"(c[3])
        : "r"(a[0]), "r"(a[1]), "r"(a[2]), "r"(a[3]), "r"(b[0]), "r"(b[1]));
}

__device__ __forceinline__ void ldmatrix_x4(uint32_t& r0, uint32_t& r1, uint32_t& r2, uint32_t& r3, uint32_t addr) {
    asm volatile("ldmatrix.sync.aligned.m8n8.x4.shared.b16 {%0,%1,%2,%3}, [%4];"
        : "=r"(r0), "=r"(r1), "=r"(r2), "=r"(r3) : "r"(addr));
}

__device__ __forceinline__ uint32_t pack_bf16x2(float lo, float hi) {
    __nv_bfloat162 p = __float22bfloat162_rn(make_float2(lo, hi));
    return *(uint32_t*)&p;
}

__device__ __forceinline__ float ex2f(float x) {
    float y; asm("ex2.approx.f32 %0, %1;" : "=f"(y) : "f"(x)); return y;
}

// QK logits for one 16-token chunk (4 mmas). KhL pre-offset by g*24+tg*2.
__device__ __forceinline__ void qk_chunk(const __nv_bfloat16* KhL, int n0,
                                         const uint32_t (&aqh)[2][4], float (&cl)[2][2][4]) {
    uint32_t bk[2][2];
    #pragma unroll
    for (int nt = 0; nt < 2; ++nt) {
        const __nv_bfloat16* kp = KhL + (n0 + nt * 8) * 24;
        bk[nt][0] = *(const uint32_t*)kp;
        bk[nt][1] = *(const uint32_t*)(kp + 8);
    }
    #pragma unroll
    for (int mt = 0; mt < 2; ++mt)
        #pragma unroll
        for (int nt = 0; nt < 2; ++nt) {
            cl[mt][nt][0] = cl[mt][nt][1] = cl[mt][nt][2] = cl[mt][nt][3] = 0.f;
            mma_bf16(cl[mt][nt], aqh[mt], bk[nt]);
        }
}

// exp2 + pack + PV accumulate for one chunk (6 mmas). VhL pre-offset by g*264+tg*2.
__device__ __forceinline__ void pv_chunk(const __nv_bfloat16* VhL, int n0,
                                         float (&cl)[2][2][4], float (&co)[2][3][4]) {
    #pragma unroll
    for (int mt = 0; mt < 2; ++mt)
        #pragma unroll
        for (int nt = 0; nt < 2; ++nt)
            #pragma unroll
            for (int i = 0; i < 4; ++i)
                cl[mt][nt][i] = ex2f(cl[mt][nt][i]);
    uint32_t ap[2][4];
    #pragma unroll
    for (int mt = 0; mt < 2; ++mt) {
        ap[mt][0] = pack_bf16x2(cl[mt][0][0], cl[mt][0][1]);
        ap[mt][1] = pack_bf16x2(cl[mt][0][2], cl[mt][0][3]);
        ap[mt][2] = pack_bf16x2(cl[mt][1][0], cl[mt][1][1]);
        ap[mt][3] = pack_bf16x2(cl[mt][1][2], cl[mt][1][3]);
    }
    uint32_t bv[3][2];
    #pragma unroll
    for (int nv = 0; nv < 3; ++nv) {
        const __nv_bfloat16* vp = VhL + nv * 2112 + n0;   // 2112 = 8*264
        bv[nv][0] = *(const uint32_t*)vp;
        bv[nv][1] = *(const uint32_t*)(vp + 8);
    }
    #pragma unroll
    for (int mt = 0; mt < 2; ++mt)
        #pragma unroll
        for (int nv = 0; nv < 3; ++nv)
            mma_bf16(co[mt][nv], ap[mt], bv[nv]);
}

// smem layout (bytes):
//   Ks   [2][256][24] bf16 : 0     .. 24576   (cols 0..15 valid)
//   Vt   [2][24][264] bf16 : 24576 .. 49920   (row16 = ones, 17..23 = zeros)
//   sGw/sGb 32 f32 each    : 49920 .. 50176
//   sWqf [16][32] u32      : 50176 .. 52224   (pre-packed Wq B-frags per lane, 2048 B)
//   sWof [16][32] u32      : 52224 .. 54272   (2048 B)
//   X scratch 8 w * 2560B  : 54272 .. 74752
#define SMEM_TOTAL 74752

__global__ void __launch_bounds__(256, 2) main_kernel(
    const float* __restrict__ cost,
    const float* __restrict__ Wq,
    const float* __restrict__ Wo,
    const float* __restrict__ gnw,
    const float* __restrict__ gnb,
    const float* __restrict__ gammap,
    float* __restrict__ out)
{
    extern __shared__ char sm[];
    __nv_bfloat16* Ks = (__nv_bfloat16*)sm;
    __nv_bfloat16* Vt = (__nv_bfloat16*)(sm + 24576);
    float*    sGw  = (float*)(sm + 49920);
    float*    sGb  = (float*)(sm + 50048);
    uint32_t* sWqf = (uint32_t*)(sm + 50176);
    uint32_t* sWof = (uint32_t*)(sm + 52224);
    char*  scratch = sm + 54272;
    __shared__ float rs[256], rss[256];
    __shared__ float sMuIs[2];

    const int b   = blockIdx.x & 1;
    const int bi  = blockIdx.x >> 1;
    const int tid = threadIdx.x;
    const int wid = tid >> 5;
    const int lane = tid & 31;
    const int g  = lane >> 2;
    const int tg = lane & 3;

    // ---- GN1 stats from prologue partials (pairwise fp32 tree, double finish) ----
    {
        float ps = 0.f, pq = 0.f;
        #pragma unroll
        for (int i = tid; i < 512; i += 256) { ps += g_p1s[b * 512 + i]; pq += g_p1q[b * 512 + i]; }
        rs[tid] = ps; rss[tid] = pq;
        __syncthreads();
        for (int st = 128; st > 0; st >>= 1) {
            if (tid < st) { rs[tid] += rs[tid + st]; rss[tid] += rss[tid + st]; }
            __syncthreads();
        }
        if (tid == 0) {
            double mu  = (double)rs[0] / (double)NELEM_B;
            double var = (double)rss[0] / (double)NELEM_B - mu * mu;
            sMuIs[0] = (float)mu;
            sMuIs[1] = (float)(1.0 / sqrt(var + 1e-5));
        }
        __syncthreads();
    }
    if (tid < 32) {
        float sc = gnw[tid] * sMuIs[1];
        sGw[tid] = sc;
        sGb[tid] = gnb[tid] - sMuIs[0] * sc;
    }

    // ---- K (token-major) and V (transposed + ones column) to smem ----
    for (int i = tid; i < 512; i += 256) {          // i = h*256 + n
        int h = i >> 8, n = i & 255;
        const uint4* kp = (const uint4*)&g_Kbf[b][h][n][0];
        __nv_bfloat16* krow = Ks + i * 24;
        ((uint4*)krow)[0] = kp[0];
        *(uint4*)(krow + 8) = kp[1];
        const __nv_bfloat16* vp = &g_Vbf[b][h][n][0];
        #pragma unroll
        for (int c = 0; c < 16; ++c) Vt[(h * 24 + c) * 264 + n] = vp[c];
        Vt[(h * 24 + 16) * 264 + n] = __float2bfloat16(1.0f);
        #pragma unroll
        for (int c = 17; c < 24; ++c) Vt[(h * 24 + c) * 264 + n] = __float2bfloat16(0.0f);
    }

    // ---- pre-packed per-lane B-fragments of Wq / Wo into smem ----
    if (tid < 32) {
        #pragma unroll
        for (int nt = 0; nt < 4; ++nt)
            #pragma unroll
            for (int kc = 0; kc < 2; ++kc) {
                const float* wq = Wq + (nt * 8 + g) * 32 + kc * 16 + tg * 2;
                const float* wo = Wo + (nt * 8 + g) * 32 + kc * 16 + tg * 2;
                int j = nt * 4 + kc * 2;
                sWqf[(j + 0) * 32 + lane] = pack_bf16x2(wq[0], wq[1]);
                sWqf[(j + 1) * 32 + lane] = pack_bf16x2(wq[8], wq[9]);
                sWof[(j + 0) * 32 + lane] = pack_bf16x2(wo[0], wo[1]);
                sWof[(j + 1) * 32 + lane] = pack_bf16x2(wo[8], wo[9]);
            }
    }
    __syncthreads();

    const float gamma = *gammap;
    const float* costb = cost + (size_t)b * NELEM_B;
    float* outb = out + (size_t)b * NELEM_B;

    __nv_bfloat16* X = (__nv_bfloat16*)(scratch + wid * 2560);  // [32][40] bf16
    const uint32_t xu = (uint32_t)__cvta_generic_to_shared(X);

    float lsum = 0.f, lsumsq = 0.f;

    for (int super = bi; super < 768; super += 148) {
        const int vbase = super * 256 + wid * 32;
        const int v = vbase + lane;

        // ---- GN1-normalize -> bf16 X in smem ----
        {
            uint32_t xp[16];
            #pragma unroll
            for (int j = 0; j < 16; ++j) {
                float a0 = fmaf(costb[(size_t)(2 * j) * SPATIAL + v],     sGw[2 * j],     sGb[2 * j]);
                float a1 = fmaf(costb[(size_t)(2 * j + 1) * SPATIAL + v], sGw[2 * j + 1], sGb[2 * j + 1]);
                xp[j] = pack_bf16x2(a0, a1);
            }
            uint4* xr = (uint4*)((char*)X + lane * 80);
            xr[0] = make_uint4(xp[0], xp[1], xp[2], xp[3]);
            xr[1] = make_uint4(xp[4], xp[5], xp[6], xp[7]);
            xr[2] = make_uint4(xp[8], xp[9], xp[10], xp[11]);
            xr[3] = make_uint4(xp[12], xp[13], xp[14], xp[15]);
        }
        __syncwarp();

        // ---- A-fragments of X via ldmatrix ----
        uint32_t aX[2][2][4];
        {
            const uint32_t lrow = (uint32_t)(lane & 15) * 80 + (uint32_t)(lane >> 4) * 16;
            #pragma unroll
            for (int mt = 0; mt < 2; ++mt)
                #pragma unroll
                for (int kc = 0; kc < 2; ++kc)
                    ldmatrix_x4(aX[mt][kc][0], aX[mt][kc][1], aX[mt][kc][2], aX[mt][kc][3],
                                xu + (uint32_t)mt * 1280 + (uint32_t)kc * 32 + lrow);
        }
        __syncwarp();  // X reads done before next iteration's writes

        // ---- q = X @ Wq^T (frags from smem; registers transient) ----
        float qc[2][4][4];
        {
            uint32_t bwqf[16];
            #pragma unroll
            for (int j = 0; j < 16; ++j) bwqf[j] = sWqf[j * 32 + lane];
            #pragma unroll
            for (int mt = 0; mt < 2; ++mt)
                #pragma unroll
                for (int nt = 0; nt < 4; ++nt) {
                    #pragma unroll
                    for (int i = 0; i < 4; ++i) qc[mt][nt][i] = 0.f;
                    mma_bf16(qc[mt][nt], aX[mt][0], &bwqf[nt * 4 + 0]);
                    mma_bf16(qc[mt][nt], aX[mt][1], &bwqf[nt * 4 + 2]);
                }
        }

        // C-frag -> A-frag identity: per-head QK A operands
        uint32_t aq[2][2][4];
        #pragma unroll
        for (int h = 0; h < 2; ++h)
            #pragma unroll
            for (int mt = 0; mt < 2; ++mt) {
                aq[h][mt][0] = pack_bf16x2(qc[mt][2 * h][0],     qc[mt][2 * h][1]);
                aq[h][mt][1] = pack_bf16x2(qc[mt][2 * h][2],     qc[mt][2 * h][3]);
                aq[h][mt][2] = pack_bf16x2(qc[mt][2 * h + 1][0], qc[mt][2 * h + 1][1]);
                aq[h][mt][3] = pack_bf16x2(qc[mt][2 * h + 1][2], qc[mt][2 * h + 1][3]);
            }

        // ---- attention per head, software-pipelined chunks ----
        uint32_t aA[2][2][4];   // [mt][kc=h][4]
        #pragma unroll
        for (int h = 0; h < 2; ++h) {
            const __nv_bfloat16* KhL = Ks + h * 6144 + g * 24  + tg * 2;
            const __nv_bfloat16* VhL = Vt + h * 6336 + g * 264 + tg * 2;
            float co[2][3][4];
            #pragma unroll
            for (int mt = 0; mt < 2; ++mt)
                #pragma unroll
                for (int nv = 0; nv < 3; ++nv)
                    #pragma unroll
                    for (int i = 0; i < 4; ++i) co[mt][nv][i] = 0.f;

            float clA[2][2][4], clB[2][2][4];
            qk_chunk(KhL, 0, aq[h], clA);
            #pragma unroll
            for (int cc = 0; cc < 8; ++cc) {
                qk_chunk(KhL, (2 * cc + 1) * 16, aq[h], clB);   // prefetch next QK
                pv_chunk(VhL, (2 * cc) * 16, clA, co);
                if (cc < 7) qk_chunk(KhL, (2 * cc + 2) * 16, aq[h], clA);
                pv_chunk(VhL, (2 * cc + 1) * 16, clB, co);
            }

            // normalize (ones-column denominator: dv16 -> tile 2, col 0) and pack
            #pragma unroll
            for (int mt = 0; mt < 2; ++mt) {
                float dlo = __shfl_sync(0xffffffffu, co[mt][2][0], lane & ~3);
                float dhi = __shfl_sync(0xffffffffu, co[mt][2][2], lane & ~3);
                float ilo = 1.f / dlo, ihi = 1.f / dhi;
                aA[mt][h][0] = pack_bf16x2(co[mt][0][0] * ilo, co[mt][0][1] * ilo);
                aA[mt][h][1] = pack_bf16x2(co[mt][0][2] * ihi, co[mt][0][3] * ihi);
                aA[mt][h][2] = pack_bf16x2(co[mt][1][0] * ilo, co[mt][1][1] * ilo);
                aA[mt][h][3] = pack_bf16x2(co[mt][1][2] * ihi, co[mt][1][3] * ihi);
            }
        }

        // ---- y = ao @ Wo^T (frags from smem) ----
        float yc[2][4][4];
        {
            uint32_t bwof[16];
            #pragma unroll
            for (int j = 0; j < 16; ++j) bwof[j] = sWof[j * 32 + lane];
            #pragma unroll
            for (int mt = 0; mt < 2; ++mt)
                #pragma unroll
                for (int nt = 0; nt < 4; ++nt) {
                    #pragma unroll
                    for (int i = 0; i < 4; ++i) yc[mt][nt][i] = 0.f;
                    mma_bf16(yc[mt][nt], aA[mt][0], &bwof[nt * 4 + 0]);
                    mma_bf16(yc[mt][nt], aA[mt][1], &bwof[nt * 4 + 2]);
                }
        }

        // ---- epilogue on fragments: residual + store + GN2 stats (incremental addressing) ----
        #pragma unroll
        for (int mt = 0; mt < 2; ++mt) {
            const size_t base = (size_t)(tg * 2) * SPATIAL + (size_t)(vbase + mt * 16 + g);
            const float* cp = costb + base;
            float*       op = outb  + base;
            #pragma unroll
            for (int nt = 0; nt < 4; ++nt) {
                float y0 = fmaf(gamma, yc[mt][nt][0], cp[0]);
                float y1 = fmaf(gamma, yc[mt][nt][1], cp[SPATIAL]);
                float y2 = fmaf(gamma, yc[mt][nt][2], cp[8]);
                float y3 = fmaf(gamma, yc[mt][nt][3], cp[SPATIAL + 8]);
                op[0] = y0; op[SPATIAL] = y1; op[8] = y2; op[SPATIAL + 8] = y3;
                lsum += (y0 + y1) + (y2 + y3);
                lsumsq = fmaf(y0, y0, lsumsq);
                lsumsq = fmaf(y1, y1, lsumsq);
                lsumsq = fmaf(y2, y2, lsumsq);
                lsumsq = fmaf(y3, y3, lsumsq);
                cp += (size_t)8 * SPATIAL;
                op += (size_t)8 * SPATIAL;
            }
        }
    }

    __syncthreads();
    rs[tid] = lsum; rss[tid] = lsumsq;
    __syncthreads();
    for (int st = 128; st > 0; st >>= 1) {
        if (tid < st) { rs[tid] += rs[tid + st]; rss[tid] += rss[tid + st]; }
        __syncthreads();
    }
    if (tid == 0) { g_p2s[blockIdx.x] = rs[0]; g_p2q[blockIdx.x] = rss[0]; }
}

// Final GroupNorm over y (in place on d_out); reduces the 296 GN2 partials per block
__global__ void gn2_kernel(float* __restrict__ y,
                           const float* __restrict__ w,
                           const float* __restrict__ bb) {
    __shared__ float4 red[256];
    __shared__ float prm[4];
    const int tid = threadIdx.x;
    {
        float s0 = 0.f, q0 = 0.f, s1 = 0.f, q1 = 0.f;
        for (int i = tid; i < 296; i += 256) {
            float s = g_p2s[i], q = g_p2q[i];
            if (i & 1) { s1 += s; q1 += q; } else { s0 += s; q0 += q; }
        }
        red[tid] = make_float4(s0, q0, s1, q1);
        __syncthreads();
        for (int st = 128; st > 0; st >>= 1) {
            if (tid < st) {
                float4 a = red[tid], c = red[tid + st];
                red[tid] = make_float4(a.x + c.x, a.y + c.y, a.z + c.z, a.w + c.w);
            }
            __syncthreads();
        }
        if (tid == 0) {
            double N = (double)NELEM_B;
            double mu0 = red[0].x / N, v0 = red[0].y / N - mu0 * mu0;
            double mu1 = red[0].z / N, v1 = red[0].w / N - mu1 * mu1;
            prm[0] = (float)mu0; prm[1] = (float)(1.0 / sqrt(v0 + 1e-5));
            prm[2] = (float)mu1; prm[3] = (float)(1.0 / sqrt(v1 + 1e-5));
        }
        __syncthreads();
    }
    const float m0 = prm[0], is0 = prm[1], m1 = prm[2], is1 = prm[3];

    const int half4  = NELEM_B / 4;
    const int total4 = 2 * half4;
    float4* p = (float4*)y;
    for (int i = blockIdx.x * blockDim.x + tid; i < total4; i += gridDim.x * blockDim.x) {
        int b = (i >= half4);
        int e = (i - b * half4) * 4;
        int c = e / SPATIAL;
        float is = b ? is1 : is0;
        float mu = b ? m1  : m0;
        float sc = w[c] * is;
        float sh = bb[c] - mu * sc;
        float4 val = p[i];
        val.x = fmaf(val.x, sc, sh);
        val.y = fmaf(val.y, sc, sh);
        val.z = fmaf(val.z, sc, sh);
        val.w = fmaf(val.w, sc, sh);
        p[i] = val;
    }
}

extern "C" void kernel_launch(void* const* d_in, const int* in_sizes, int n_in,
                              void* d_out, int out_size) {
    const float* cost   = (const float*)d_in[0];
    const float* feat   = (const float*)d_in[1];
    const float* Wq     = (const float*)d_in[2];
    const float* Wk     = (const float*)d_in[3];
    const float* Wv     = (const float*)d_in[4];
    const float* Wo     = (const float*)d_in[5];
    const float* gn_in_w  = (const float*)d_in[6];
    const float* gn_in_b  = (const float*)d_in[7];
    const float* gn_out_w = (const float*)d_in[8];
    const float* gn_out_b = (const float*)d_in[9];
    const float* gamma    = (const float*)d_in[10];
    float* out = (float*)d_out;

    cudaFuncSetAttribute(main_kernel, cudaFuncAttributeMaxDynamicSharedMemorySize, SMEM_TOTAL);

    prologue_kernel<<<1088, 256>>>(cost, feat, Wk, Wv);
    main_kernel<<<296, 256, SMEM_TOTAL>>>(cost, Wq, Wo, gn_in_w, gn_in_b, gamma, out);
    gn2_kernel<<<2368, 256>>>(out, gn_out_w, gn_out_b);
}